// round 8
// baseline (speedup 1.0000x reference)
#include <cuda_runtime.h>
#include <cstdint>
#include <math.h>

// GumbelSlotSelector — fused fp32, packed fma.rn.f32x2, 2 CTAs/SM.
// Shapes: B=256, K=512, D=256, H=256.  Output: [hard_mask(131072), soft_prob(131072)] f32.

static constexpr int B_   = 256;
static constexpr int K_   = 512;
static constexpr int BK   = B_ * K_;      // 131072 rows
static constexpr int D_   = 256;
static constexpr int H_   = 256;
static constexpr int MT   = 64;           // rows per block (smaller tile -> 2 CTAs/SM)
static constexpr int NBLK = BK / MT;      // 2048 blocks
static constexpr int BPB  = K_ / MT;      // blocks per batch row = 8
static constexpr int KCH  = 16;           // k-chunk of W1 staged in smem
static constexpr int NCH  = D_ / KCH;     // 16 chunks
static constexpr float LN_EPS = 1e-5f;

__device__ int g_partial[NBLK];           // per-block kept count (plain store, no init needed)

struct __align__(16) Smem {
    float4 w1s[2][KCH * (H_ / 4)];        // double-buffered W1 chunk: 2 x 16KB
    float  xs[MT * D_];                   // LN'd activations: 64KB
    float  mu[MT];
    float  rs[MT];
    float  b1s[H_];
    float2 w2s[H_];
    float  gs[D_];
    float  bs[D_];
    int    cnt;
};                                        // ~99.3 KB -> two CTAs fit in 228KB

__device__ __forceinline__ void cp16(void* s, const void* g) {
    uint32_t sa = (uint32_t)__cvta_generic_to_shared(s);
    asm volatile("cp.async.cg.shared.global [%0], [%1], 16;" :: "r"(sa), "l"(g));
}
__device__ __forceinline__ void cp_commit() { asm volatile("cp.async.commit_group;"); }
template <int N>
__device__ __forceinline__ void cp_wait() { asm volatile("cp.async.wait_group %0;" :: "n"(N)); }

// packed f32x2 FMA: d.lo += a.lo*b.lo ; d.hi += a.hi*b.hi  (rn, identical to scalar fmaf)
__device__ __forceinline__ void ffma2(unsigned long long& d,
                                      unsigned long long a,
                                      unsigned long long b) {
    asm("fma.rn.f32x2 %0, %1, %2, %0;" : "+l"(d) : "l"(a), "l"(b));
}
__device__ __forceinline__ unsigned long long bcast2(float a) {
    unsigned long long r;
    asm("mov.b64 %0, {%1, %1};" : "=l"(r) : "f"(a));
    return r;
}

__global__ void __launch_bounds__(256, 2) fused_kernel(
    const float* __restrict__ slots,
    const float* __restrict__ lng,
    const float* __restrict__ lnb,
    const float* __restrict__ w1,
    const float* __restrict__ b1,
    const float* __restrict__ w2,
    const float* __restrict__ b2,
    const float* __restrict__ uu,
    float* __restrict__ out_hard,
    float* __restrict__ out_soft)
{
    extern __shared__ char smraw[];
    Smem& sm = *reinterpret_cast<Smem*>(smraw);
    const int tid = threadIdx.x;
    const int base_row = blockIdx.x * MT;

    // ---- async stage: slots tile (group 0), W1 chunk 0 (group 1) ----
    const float4* src = reinterpret_cast<const float4*>(slots) + (size_t)base_row * (D_ / 4);
    float4* xs4 = reinterpret_cast<float4*>(sm.xs);
    #pragma unroll
    for (int t = 0; t < (MT * D_ / 4) / 256; t++)       // 16 per thread
        cp16(&xs4[tid + t * 256], &src[tid + t * 256]);
    cp_commit();

    const float4* w1_4 = reinterpret_cast<const float4*>(w1);
    #pragma unroll
    for (int t = 0; t < (KCH * H_ / 4) / 256; t++)      // 4 per thread
        cp16(&sm.w1s[0][tid + t * 256], &w1_4[tid + t * 256]);
    cp_commit();

    // small params via regular loads (latency hidden behind LN)
    sm.gs[tid]  = lng[tid];
    sm.bs[tid]  = lnb[tid];
    sm.b1s[tid] = b1[tid];
    sm.w2s[tid] = make_float2(w2[2 * tid], w2[2 * tid + 1]);
    if (tid == 0) sm.cnt = 0;

    cp_wait<1>();            // slots tile arrived (W1 chunk0 may still be in flight)
    __syncthreads();

    // ---- LayerNorm: one warp per row (conflict-free, butterfly reduce) ----
    const int lane = tid & 31, warp = tid >> 5;
    for (int r = warp; r < MT; r += 8) {
        const float* row = sm.xs + r * D_;
        float s = 0.f;
        #pragma unroll
        for (int m = 0; m < D_ / 32; m++) s += row[lane + m * 32];
        #pragma unroll
        for (int o = 16; o; o >>= 1) s += __shfl_xor_sync(0xffffffffu, s, o);
        float mean = s * (1.f / D_);
        float v = 0.f;
        #pragma unroll
        for (int m = 0; m < D_ / 32; m++) {
            float d = row[lane + m * 32] - mean;
            v = fmaf(d, d, v);
        }
        #pragma unroll
        for (int o = 16; o; o >>= 1) v += __shfl_xor_sync(0xffffffffu, v, o);
        if (lane == 0) {
            sm.mu[r] = mean;
            sm.rs[r] = 1.f / sqrtf(v * (1.f / D_) + LN_EPS);
        }
    }
    __syncthreads();
    // normalize in place: thread owns one column, walks rows (conflict-free)
    #pragma unroll 4
    for (int r = 0; r < MT; r++) {
        int idx = tid + r * D_;
        float vx = sm.xs[idx];
        sm.xs[idx] = (vx - sm.mu[r]) * sm.rs[r] * sm.gs[tid] + sm.bs[tid];
    }
    __syncthreads();

    // ---- GEMM1: 64x256x256, thread tile 4 rows x 16 cols (8 f32x2 pairs) ----
    const int tx = tid & 15, ty = tid >> 4;
    unsigned long long acc2[4][8];
    #pragma unroll
    for (int i = 0; i < 4; i++)
        #pragma unroll
        for (int p = 0; p < 8; p++) acc2[i][p] = 0ull;

    const float* xbase = sm.xs + (ty * 4) * D_;

    for (int c = 0; c < NCH; c++) {
        if (c + 1 < NCH) {
            #pragma unroll
            for (int t = 0; t < (KCH * H_ / 4) / 256; t++)
                cp16(&sm.w1s[(c + 1) & 1][tid + t * 256],
                     &w1_4[(c + 1) * (KCH * H_ / 4) + tid + t * 256]);
            cp_commit();
            cp_wait<1>();    // current chunk's group complete; newest pending
        } else {
            cp_wait<0>();
        }
        __syncthreads();

        // W1 chunk as ulonglong2 (16B = 2 packed f32x2 pairs). Row of 256 floats
        // = 64 ulonglong2 -> row stride 64.
        const ulonglong2* wb2 = reinterpret_cast<const ulonglong2*>(sm.w1s[c & 1]);
        #pragma unroll 1
        for (int kk = 0; kk < KCH; kk += 4) {
            float4 a4[4];
            #pragma unroll
            for (int i = 0; i < 4; i++)
                a4[i] = *reinterpret_cast<const float4*>(xbase + i * D_ + c * KCH + kk);
            #pragma unroll
            for (int t = 0; t < 4; t++) {
                const ulonglong2* wrow = wb2 + (kk + t) * 64 + tx * 4;
                ulonglong2 q0 = wrow[0], q1 = wrow[1], q2 = wrow[2], q3 = wrow[3];
                #pragma unroll
                for (int i = 0; i < 4; i++) {
                    unsigned long long ap = bcast2((&a4[i].x)[t]);
                    ffma2(acc2[i][0], ap, q0.x);
                    ffma2(acc2[i][1], ap, q0.y);
                    ffma2(acc2[i][2], ap, q1.x);
                    ffma2(acc2[i][3], ap, q1.y);
                    ffma2(acc2[i][4], ap, q2.x);
                    ffma2(acc2[i][5], ap, q2.y);
                    ffma2(acc2[i][6], ap, q3.x);
                    ffma2(acc2[i][7], ap, q3.y);
                }
            }
        }
        __syncthreads();
    }

    // ---- epilogue: bias+relu, GEMM2 (H->2), gumbel decision, soft prob ----
    float b20 = b2[0], b21 = b2[1];
    int myhard = 0;
    #pragma unroll
    for (int i = 0; i < 4; i++) {
        float p0 = 0.f, p1 = 0.f;
        #pragma unroll
        for (int p = 0; p < 8; p++) {
            union { unsigned long long u; float2 f; } cvt;
            cvt.u = acc2[i][p];
            int cc = tx * 16 + 2 * p;
            float h0 = fmaxf(cvt.f.x + sm.b1s[cc], 0.f);
            float h1 = fmaxf(cvt.f.y + sm.b1s[cc + 1], 0.f);
            float2 wA = sm.w2s[cc];
            float2 wB = sm.w2s[cc + 1];
            p0 = fmaf(h0, wA.x, p0); p1 = fmaf(h0, wA.y, p1);
            p0 = fmaf(h1, wB.x, p0); p1 = fmaf(h1, wB.y, p1);
        }
        // reduce over the 16 col-lanes (xor stays within the 16-group)
        #pragma unroll
        for (int o = 8; o; o >>= 1) {
            p0 += __shfl_xor_sync(0xffffffffu, p0, o);
            p1 += __shfl_xor_sync(0xffffffffu, p1, o);
        }
        if (tx == i) {      // lane i of each 16-group finalizes row (ty*4+i)
            int row = base_row + ty * 4 + i;
            float l0 = p0 + b20, l1 = p1 + b21;
            float soft = 1.f / (1.f + expf(l0 - l1));   // softmax(logits)[1]
            float u0 = uu[2 * row], u1 = uu[2 * row + 1];
            float z0 = l0 - logf(-logf(u0));            // logits + gumbel, tau=1
            float z1 = l1 - logf(-logf(u1));
            int hard = (z1 > z0) ? 1 : 0;               // tie -> argmax picks 0
            out_hard[row] = (float)hard;
            out_soft[row] = soft;
            myhard = hard;
        }
    }
    unsigned mvote = __ballot_sync(0xffffffffu, myhard != 0);
    if (lane == 0) atomicAdd(&sm.cnt, __popc(mvote));
    __syncthreads();
    if (tid == 0) g_partial[blockIdx.x] = sm.cnt;   // plain store — no pre-zero needed
}

// Lower-bound resample: if a batch row kept nothing, keep the dropped slot with
// the max rand_key (stable tie-break -> lowest index, matching double-argsort).
__global__ void __launch_bounds__(256) resample_kernel(
    const float* __restrict__ rk, float* __restrict__ out_hard)
{
    __shared__ float vs[256];
    __shared__ int   is_[256];
    const int b = blockIdx.x, tid = threadIdx.x;
    int kept = 0;
    #pragma unroll
    for (int j = 0; j < BPB; j++) kept += g_partial[b * BPB + j];
    if (kept > 0) return;                 // uniform branch per block
    const float* r = rk + b * K_;
    float v0 = r[tid], v1 = r[tid + 256];
    float v; int idx;
    if (v0 >= v1) { v = v0; idx = tid; } else { v = v1; idx = tid + 256; }
    vs[tid] = v; is_[tid] = idx;
    __syncthreads();
    for (int s = 128; s; s >>= 1) {
        if (tid < s) {
            float ov = vs[tid + s]; int oi = is_[tid + s];
            if (ov > vs[tid] || (ov == vs[tid] && oi < is_[tid])) {
                vs[tid] = ov; is_[tid] = oi;
            }
        }
        __syncthreads();
    }
    if (tid == 0) out_hard[b * K_ + is_[0]] = 1.f;
}

extern "C" void kernel_launch(void* const* d_in, const int* in_sizes, int n_in,
                              void* d_out, int out_size)
{
    const float* slots = (const float*)d_in[0];
    const float* lng   = (const float*)d_in[1];
    const float* lnb   = (const float*)d_in[2];
    const float* w1    = (const float*)d_in[3];
    const float* b1    = (const float*)d_in[4];
    const float* w2    = (const float*)d_in[5];
    const float* b2    = (const float*)d_in[6];
    const float* uu    = (const float*)d_in[7];
    const float* rk    = (const float*)d_in[8];
    float* out_hard = (float*)d_out;
    float* out_soft = out_hard + BK;

    cudaFuncSetAttribute(fused_kernel,
                         cudaFuncAttributeMaxDynamicSharedMemorySize,
                         (int)sizeof(Smem));

    fused_kernel<<<NBLK, 256, sizeof(Smem)>>>(slots, lng, lnb, w1, b1, w2, b2,
                                              uu, out_hard, out_soft);
    resample_kernel<<<B_, 256>>>(rk, out_hard);
}

// round 10
// speedup vs baseline: 2.5714x; 2.5714x over previous
#include <cuda_runtime.h>
#include <cstdint>
#include <math.h>

// GumbelSlotSelector — fused fp32, packed fma.rn.f32x2, conflict-free W layout.
// Shapes: B=256, K=512, D=256, H=256.  Output: [hard_mask(131072), soft_prob(131072)] f32.

static constexpr int B_   = 256;
static constexpr int K_   = 512;
static constexpr int BK   = B_ * K_;      // 131072 rows
static constexpr int D_   = 256;
static constexpr int H_   = 256;
static constexpr int MT   = 128;          // rows per block
static constexpr int NBLK = BK / MT;      // 1024 blocks
static constexpr int BPB  = K_ / MT;      // blocks per batch row = 4
static constexpr int KCH  = 32;           // k-chunk of W1 staged in smem
static constexpr int NCH  = D_ / KCH;     // 8 chunks
static constexpr float LN_EPS = 1e-5f;

__device__ int g_partial[NBLK];           // per-block kept count (plain store, no init needed)

struct __align__(16) Smem {
    float4 w1s[2][KCH * (H_ / 4)];        // double-buffered W1 chunk: 2 x 32KB
    float  xs[MT * D_];                   // LN'd activations: 128KB
    float  mu[MT];
    float  rs[MT];
    float  b1s[H_];
    float2 w2s[H_];
    float  gs[D_];
    float  bs[D_];
    int    cnt;
};

__device__ __forceinline__ void cp16(void* s, const void* g) {
    uint32_t sa = (uint32_t)__cvta_generic_to_shared(s);
    asm volatile("cp.async.cg.shared.global [%0], [%1], 16;" :: "r"(sa), "l"(g));
}
__device__ __forceinline__ void cp_commit() { asm volatile("cp.async.commit_group;"); }
template <int N>
__device__ __forceinline__ void cp_wait() { asm volatile("cp.async.wait_group %0;" :: "n"(N)); }

// packed f32x2 FMA: d.lo += a.lo*b.lo ; d.hi += a.hi*b.hi  (rn, identical to scalar fmaf)
__device__ __forceinline__ void ffma2(unsigned long long& d,
                                      unsigned long long a,
                                      unsigned long long b) {
    asm("fma.rn.f32x2 %0, %1, %2, %0;" : "+l"(d) : "l"(a), "l"(b));
}
__device__ __forceinline__ unsigned long long bcast2(float a) {
    unsigned long long r;
    asm("mov.b64 %0, {%1, %1};" : "=l"(r) : "f"(a));
    return r;
}

__global__ void __launch_bounds__(256, 1) fused_kernel(
    const float* __restrict__ slots,
    const float* __restrict__ lng,
    const float* __restrict__ lnb,
    const float* __restrict__ w1,
    const float* __restrict__ b1,
    const float* __restrict__ w2,
    const float* __restrict__ b2,
    const float* __restrict__ uu,
    float* __restrict__ out_hard,
    float* __restrict__ out_soft)
{
    extern __shared__ char smraw[];
    Smem& sm = *reinterpret_cast<Smem*>(smraw);
    const int tid = threadIdx.x;
    const int base_row = blockIdx.x * MT;

    // ---- async stage: slots tile (group 0), W1 chunk 0 (group 1) ----
    const float4* src = reinterpret_cast<const float4*>(slots) + (size_t)base_row * (D_ / 4);
    float4* xs4 = reinterpret_cast<float4*>(sm.xs);
    #pragma unroll
    for (int t = 0; t < (MT * D_ / 4) / 256; t++)       // 32 per thread
        cp16(&xs4[tid + t * 256], &src[tid + t * 256]);
    cp_commit();

    const float4* w1_4 = reinterpret_cast<const float4*>(w1);
    #pragma unroll
    for (int t = 0; t < 8; t++)
        cp16(&sm.w1s[0][tid + t * 256], &w1_4[tid + t * 256]);
    cp_commit();

    // small params via regular loads (latency hidden behind LN)
    sm.gs[tid]  = lng[tid];
    sm.bs[tid]  = lnb[tid];
    sm.b1s[tid] = b1[tid];
    sm.w2s[tid] = make_float2(w2[2 * tid], w2[2 * tid + 1]);
    if (tid == 0) sm.cnt = 0;

    cp_wait<1>();            // slots tile arrived (W1 chunk0 may still be in flight)
    __syncthreads();

    // ---- LayerNorm: one warp per row (conflict-free, butterfly reduce) ----
    const int lane = tid & 31, warp = tid >> 5;
    for (int r = warp; r < MT; r += 8) {
        const float* row = sm.xs + r * D_;
        float s = 0.f;
        #pragma unroll
        for (int m = 0; m < D_ / 32; m++) s += row[lane + m * 32];
        #pragma unroll
        for (int o = 16; o; o >>= 1) s += __shfl_xor_sync(0xffffffffu, s, o);
        float mean = s * (1.f / D_);
        float v = 0.f;
        #pragma unroll
        for (int m = 0; m < D_ / 32; m++) {
            float d = row[lane + m * 32] - mean;
            v = fmaf(d, d, v);
        }
        #pragma unroll
        for (int o = 16; o; o >>= 1) v += __shfl_xor_sync(0xffffffffu, v, o);
        if (lane == 0) {
            sm.mu[r] = mean;
            sm.rs[r] = 1.f / sqrtf(v * (1.f / D_) + LN_EPS);
        }
    }
    __syncthreads();
    // normalize in place: thread owns one column, walks rows (conflict-free)
    #pragma unroll 4
    for (int r = 0; r < MT; r++) {
        int idx = tid + r * D_;
        float vx = sm.xs[idx];
        sm.xs[idx] = (vx - sm.mu[r]) * sm.rs[r] * sm.gs[tid] + sm.bs[tid];
    }
    __syncthreads();

    // ---- GEMM1: 128x256x256, thread tile 8 rows x 16 cols (8 f32x2 pairs) ----
    // Column ownership is INTERLEAVED for bank-conflict-free W loads:
    // thread tx owns ulonglong2 indices {tx, tx+16, tx+32, tx+48} of each W row
    // (byte offset tx*16 + j*256 -> each 8-thread LDS phase covers a contiguous
    //  128B = all 32 banks distinct; the old tx*4 layout was a 4-way conflict).
    const int tx = tid & 15, ty = tid >> 4;
    unsigned long long acc2[8][8];
    #pragma unroll
    for (int i = 0; i < 8; i++)
        #pragma unroll
        for (int p = 0; p < 8; p++) acc2[i][p] = 0ull;

    const float* xbase = sm.xs + (ty * 8) * D_;

    for (int c = 0; c < NCH; c++) {
        if (c + 1 < NCH) {
            #pragma unroll
            for (int t = 0; t < 8; t++)
                cp16(&sm.w1s[(c + 1) & 1][tid + t * 256],
                     &w1_4[(c + 1) * (KCH * H_ / 4) + tid + t * 256]);
            cp_commit();
            cp_wait<1>();    // current chunk's group complete; newest pending
        } else {
            cp_wait<0>();
        }
        __syncthreads();

        // W1 chunk as ulonglong2 (16B = 2 packed f32x2 pairs); row stride 64.
        const ulonglong2* wb2 = reinterpret_cast<const ulonglong2*>(sm.w1s[c & 1]);
        #pragma unroll 1
        for (int kk = 0; kk < KCH; kk += 4) {
            float4 a4[8];
            #pragma unroll
            for (int i = 0; i < 8; i++)
                a4[i] = *reinterpret_cast<const float4*>(xbase + i * D_ + c * KCH + kk);
            #pragma unroll
            for (int t = 0; t < 4; t++) {
                const ulonglong2* wrow = wb2 + (kk + t) * 64 + tx;
                ulonglong2 q0 = wrow[0];        // cols 4*(tx+ 0)..+3
                ulonglong2 q1 = wrow[16];       // cols 4*(tx+16)..+3
                ulonglong2 q2 = wrow[32];       // cols 4*(tx+32)..+3
                ulonglong2 q3 = wrow[48];       // cols 4*(tx+48)..+3
                #pragma unroll
                for (int i = 0; i < 8; i++) {
                    unsigned long long ap = bcast2((&a4[i].x)[t]);
                    ffma2(acc2[i][0], ap, q0.x);
                    ffma2(acc2[i][1], ap, q0.y);
                    ffma2(acc2[i][2], ap, q1.x);
                    ffma2(acc2[i][3], ap, q1.y);
                    ffma2(acc2[i][4], ap, q2.x);
                    ffma2(acc2[i][5], ap, q2.y);
                    ffma2(acc2[i][6], ap, q3.x);
                    ffma2(acc2[i][7], ap, q3.y);
                }
            }
        }
        __syncthreads();
    }

    // ---- epilogue: bias+relu, GEMM2 (H->2), gumbel decision, soft prob ----
    // pair p = 2*j + h  ->  columns cc = 4*(tx + 16*j) + 2*h, cc+1
    float b20 = b2[0], b21 = b2[1];
    int myhard = 0;
    #pragma unroll
    for (int i = 0; i < 8; i++) {
        float p0 = 0.f, p1 = 0.f;
        #pragma unroll
        for (int p = 0; p < 8; p++) {
            union { unsigned long long u; float2 f; } cvt;
            cvt.u = acc2[i][p];
            int j = p >> 1, h = p & 1;
            int cc = 4 * (tx + 16 * j) + 2 * h;
            float h0 = fmaxf(cvt.f.x + sm.b1s[cc], 0.f);
            float h1 = fmaxf(cvt.f.y + sm.b1s[cc + 1], 0.f);
            float2 wA = sm.w2s[cc];
            float2 wB = sm.w2s[cc + 1];
            p0 = fmaf(h0, wA.x, p0); p1 = fmaf(h0, wA.y, p1);
            p0 = fmaf(h1, wB.x, p0); p1 = fmaf(h1, wB.y, p1);
        }
        // reduce over the 16 col-lanes (xor stays within the 16-group);
        // union of columns over tx = all 256, so the sum is the full dot.
        #pragma unroll
        for (int o = 8; o; o >>= 1) {
            p0 += __shfl_xor_sync(0xffffffffu, p0, o);
            p1 += __shfl_xor_sync(0xffffffffu, p1, o);
        }
        if (tx == i) {      // lane i of each 16-group finalizes row (ty*8+i)
            int row = base_row + ty * 8 + i;
            float l0 = p0 + b20, l1 = p1 + b21;
            float soft = 1.f / (1.f + expf(l0 - l1));   // softmax(logits)[1]
            float u0 = uu[2 * row], u1 = uu[2 * row + 1];
            float z0 = l0 - logf(-logf(u0));            // logits + gumbel, tau=1
            float z1 = l1 - logf(-logf(u1));
            int hard = (z1 > z0) ? 1 : 0;               // tie -> argmax picks 0
            out_hard[row] = (float)hard;
            out_soft[row] = soft;
            myhard = hard;
        }
    }
    unsigned mvote = __ballot_sync(0xffffffffu, myhard != 0);
    if (lane == 0) atomicAdd(&sm.cnt, __popc(mvote));
    __syncthreads();
    if (tid == 0) g_partial[blockIdx.x] = sm.cnt;   // plain store — no pre-zero needed
}

// Lower-bound resample: if a batch row kept nothing, keep the dropped slot with
// the max rand_key (stable tie-break -> lowest index, matching double-argsort).
__global__ void __launch_bounds__(256) resample_kernel(
    const float* __restrict__ rk, float* __restrict__ out_hard)
{
    __shared__ float vs[256];
    __shared__ int   is_[256];
    const int b = blockIdx.x, tid = threadIdx.x;
    int kept = 0;
    #pragma unroll
    for (int j = 0; j < BPB; j++) kept += g_partial[b * BPB + j];
    if (kept > 0) return;                 // uniform branch per block
    const float* r = rk + b * K_;
    float v0 = r[tid], v1 = r[tid + 256];
    float v; int idx;
    if (v0 >= v1) { v = v0; idx = tid; } else { v = v1; idx = tid + 256; }
    vs[tid] = v; is_[tid] = idx;
    __syncthreads();
    for (int s = 128; s; s >>= 1) {
        if (tid < s) {
            float ov = vs[tid + s]; int oi = is_[tid + s];
            if (ov > vs[tid] || (ov == vs[tid] && oi < is_[tid])) {
                vs[tid] = ov; is_[tid] = oi;
            }
        }
        __syncthreads();
    }
    if (tid == 0) out_hard[b * K_ + is_[0]] = 1.f;
}

extern "C" void kernel_launch(void* const* d_in, const int* in_sizes, int n_in,
                              void* d_out, int out_size)
{
    const float* slots = (const float*)d_in[0];
    const float* lng   = (const float*)d_in[1];
    const float* lnb   = (const float*)d_in[2];
    const float* w1    = (const float*)d_in[3];
    const float* b1    = (const float*)d_in[4];
    const float* w2    = (const float*)d_in[5];
    const float* b2    = (const float*)d_in[6];
    const float* uu    = (const float*)d_in[7];
    const float* rk    = (const float*)d_in[8];
    float* out_hard = (float*)d_out;
    float* out_soft = out_hard + BK;

    cudaFuncSetAttribute(fused_kernel,
                         cudaFuncAttributeMaxDynamicSharedMemorySize,
                         (int)sizeof(Smem));

    fused_kernel<<<NBLK, 256, sizeof(Smem)>>>(slots, lng, lnb, w1, b1, w2, b2,
                                              uu, out_hard, out_soft);
    resample_kernel<<<B_, 256>>>(rk, out_hard);
}